// round 16
// baseline (speedup 1.0000x reference)
#include <cuda_runtime.h>
#include <cuda.h>
#include <cuda_fp16.h>
#include <cstdint>

// ---------------------------------------------------------------- constants
#define BB   16
#define DD   512
#define TT   1024
#define KK   8192
#define BT   (BB * TT)
#define BDT  (BB * DD * TT)

#define EPSV 1e-5f
#define SCALE 16.0f             // argmin-invariant scaling (avoids fp16 subnormal lo)

#define KCH  16                 // 512 / 32 k-chunks
#define NBUF 3
#define A_BYTES 16384           // 128 rows x 128B
#define B_BYTES 8192            // 64 rows x 128B
#define BUF_BYTES (A_BYTES + B_BYTES)          // 24576
#define SMEM_BARS (NBUF * BUF_BYTES)           // 73728
#define SMEM_TOTAL (SMEM_BARS + 64)

#define BAR_FULL(s)  (sbu + SMEM_BARS + (s) * 8)
#define BAR_EMPTY(s) (sbu + SMEM_BARS + 24 + (s) * 8)

// ---------------------------------------------------------------- scratch
__device__ float  g_emb[(size_t)KK * DD];       // fp32 codebook (gather)
__device__ __half g_ea[(size_t)KK * KCH * 64];  // emb: [code][kc][hi x32 | lo x32]
__device__ __half g_xa[(size_t)BT * KCH * 64];  // x:   [token][kc][hi x32 | lo x32]
__device__ float  g_e2[KK];                     // 256 * ||e||^2
__device__ unsigned long long g_best[BT];       // packed (ordered-score << 32 | k)

// ---------------------------------------------------------------- helpers
__device__ __forceinline__ uint32_t smem_u32(const void* p) {
    uint32_t a;
    asm("{ .reg .u64 t; cvta.to.shared.u64 t, %1; cvt.u32.u64 %0, t; }" : "=r"(a) : "l"(p));
    return a;
}

#define MBARRIER_INIT(a, c) \
    asm volatile("mbarrier.init.shared.b64 [%0], %1;" :: "r"((uint32_t)(a)), "r"((uint32_t)(c)) : "memory")
#define MBARRIER_EXPECT_TX(a, b) \
    asm volatile("mbarrier.arrive.expect_tx.shared.b64 _, [%0], %1;" :: "r"((uint32_t)(a)), "r"((uint32_t)(b)) : "memory")
#define MBARRIER_ARRIVE(a) \
    asm volatile("mbarrier.arrive.shared.b64 _, [%0];" :: "r"((uint32_t)(a)) : "memory")

#define MBARRIER_WAIT_PARITY(mbar, ph) do { \
    uint32_t _m = (uint32_t)(mbar), _p = (uint32_t)(ph); \
    asm volatile("{\n\t.reg .pred P1;\n\t" \
        "WL_%=:\n\t" \
        "mbarrier.try_wait.parity.acquire.cta.shared::cta.b64 P1, [%0], %1, 0x989680;\n\t" \
        "@P1 bra.uni WD_%=;\n\tbra.uni WL_%=;\n\tWD_%=:\n\t}" \
        :: "r"(_m), "r"(_p) : "memory"); \
} while (0)

#define MBARRIER_WAIT_PARITY_RELAXED(mbar, ph) do { \
    uint32_t _m = (uint32_t)(mbar), _p = (uint32_t)(ph); \
    asm volatile("{\n\t.reg .pred P1;\n\t" \
        "WL_%=:\n\t" \
        "mbarrier.try_wait.parity.relaxed.cta.shared::cta.b64 P1, [%0], %1, 0x989680;\n\t" \
        "@P1 bra.uni WD_%=;\n\tbra.uni WL_%=;\n\tWD_%=:\n\t}" \
        :: "r"(_m), "r"(_p) : "memory"); \
} while (0)

#define TMA_LOAD_3D(dst, map, cx, cy, cz, mb) \
    asm volatile("cp.async.bulk.tensor.3d.shared::cta.global.tile.mbarrier::complete_tx::bytes " \
        "[%0], [%1, {%2, %3, %4}], [%5];" \
        :: "r"((uint32_t)(dst)), "l"(map), "r"((int)(cx)), "r"((int)(cy)), "r"((int)(cz)), \
           "r"((uint32_t)(mb)) : "memory")

#define LDSM4(r, addr) \
    asm volatile("ldmatrix.sync.aligned.m8n8.x4.shared.b16 {%0,%1,%2,%3}, [%4];" \
        : "=r"((r)[0]), "=r"((r)[1]), "=r"((r)[2]), "=r"((r)[3]) : "r"((uint32_t)(addr)))

__device__ __forceinline__ void mma16(float* d, const uint32_t* a,
                                      uint32_t b0, uint32_t b1) {
    asm volatile(
        "mma.sync.aligned.m16n8k16.row.col.f32.f16.f16.f32 "
        "{%0,%1,%2,%3}, {%4,%5,%6,%7}, {%8,%9}, {%0,%1,%2,%3};"
        : "+f"(d[0]), "+f"(d[1]), "+f"(d[2]), "+f"(d[3])
        : "r"(a[0]), "r"(a[1]), "r"(a[2]), "r"(a[3]), "r"(b0), "r"(b1));
}

__device__ __forceinline__ unsigned long long packsk(float s, int k) {
    uint32_t u = __float_as_uint(s);
    u ^= (uint32_t)((int32_t)u >> 31) | 0x80000000u;
    return ((unsigned long long)u << 32) | (uint32_t)k;
}
__device__ __forceinline__ unsigned long long umin64(unsigned long long a,
                                                     unsigned long long b) {
    return a < b ? a : b;
}

// ---------------------------------------------------------------- merged prep
// blocks [0, KK/2): emb prep (2 codes per 256-thread block), 8B packed ea stores
// blocks [KK/2, KK/2 + BB*KCH*(TT/64)): x transpose + split, 64 tokens x 32 d
__global__ void __launch_bounds__(256)
prep_all_kernel(const float* __restrict__ esum,
                const float* __restrict__ usage,
                const float* __restrict__ x) {
    int bid = blockIdx.x;
    if (bid < KK / 2) {
        int tid128 = threadIdx.x & 127;
        int k = bid * 2 + (threadIdx.x >> 7);
        float inv = 1.0f / fmaxf(usage[k], EPSV);

        float4 v = ((const float4*)(esum + (size_t)k * DD))[tid128];
        v.x *= inv; v.y *= inv; v.z *= inv; v.w *= inv;
        ((float4*)(g_emb + (size_t)k * DD))[tid128] = v;

        int d  = tid128 * 4;
        int kc = d >> 5, j = d & 31;
        __half* row = g_ea + ((size_t)k * KCH + kc) * 64;
        float vv[4] = {v.x, v.y, v.z, v.w};
        __half2 hh[2], ll[2];
        #pragma unroll
        for (int c = 0; c < 2; c++) {
            float f0 = vv[2 * c] * SCALE;
            float f1 = vv[2 * c + 1] * SCALE;
            __half h0 = __float2half_rn(f0);
            __half h1 = __float2half_rn(f1);
            __half l0 = __float2half_rn(f0 - __half2float(h0));
            __half l1 = __float2half_rn(f1 - __half2float(h1));
            hh[c] = __halves2half2(h0, h1);
            ll[c] = __halves2half2(l0, l1);
        }
        *(uint2*)(row + j)      = *(uint2*)hh;
        *(uint2*)(row + 32 + j) = *(uint2*)ll;

        float s = v.x * v.x + v.y * v.y + v.z * v.z + v.w * v.w;
        #pragma unroll
        for (int off = 16; off > 0; off >>= 1)
            s += __shfl_down_sync(0xFFFFFFFFu, s, off);

        __shared__ float ws[8];
        int lane = threadIdx.x & 31, w = threadIdx.x >> 5;
        if (lane == 0) ws[w] = s;
        __syncthreads();
        if (tid128 == 0) {
            int w0 = (threadIdx.x >> 7) * 4;
            g_e2[k] = (SCALE * SCALE) * (ws[w0] + ws[w0 + 1] + ws[w0 + 2] + ws[w0 + 3]);
        }
    } else {
        __shared__ float tile[32][65];
        int xid = bid - KK / 2;
        int b    = xid >> 8;
        int kc   = (xid >> 4) & 15;
        int t0   = (xid & 15) * 64;
        int tid  = threadIdx.x;
        int lane = tid & 31, w = tid >> 5;

        const float* xb = x + ((size_t)b * DD + kc * 32) * TT + t0;
        #pragma unroll
        for (int i = 0; i < 4; i++) {
            int row = w + i * 8;
            float2 v = *(const float2*)(xb + (size_t)row * TT + lane * 2);
            tile[row][lane * 2]     = v.x;
            tile[row][lane * 2 + 1] = v.y;
        }
        if (kc == 0 && tid < 64) g_best[b * TT + t0 + tid] = ~0ULL;
        __syncthreads();

        int tok = tid >> 2;
        int dg  = (tid & 3) * 8;
        __half2 h2[4], l2[4];
        #pragma unroll
        for (int j = 0; j < 4; j++) {
            float f0 = tile[dg + 2 * j][tok] * SCALE;
            float f1 = tile[dg + 2 * j + 1][tok] * SCALE;
            __half h0 = __float2half_rn(f0);
            __half h1 = __float2half_rn(f1);
            __half l0 = __float2half_rn(f0 - __half2float(h0));
            __half l1 = __float2half_rn(f1 - __half2float(h1));
            h2[j] = __halves2half2(h0, h1);
            l2[j] = __halves2half2(l0, l1);
        }
        size_t row = ((size_t)(b * TT + t0 + tok) * KCH + kc) * 64;
        *(uint4*)(g_xa + row + dg)      = *(uint4*)h2;
        *(uint4*)(g_xa + row + 32 + dg) = *(uint4*)l2;
    }
}

// ---------------------------------------------------------------- GEMM + argmin (R10/R12 proven config)
// CTA: 128(M) x 64(N), 4 consumer warps (warp tile 64x32) + 1 producer.
// 3 CTAs / SM (72KB smem) -> 3 consumer warps/SMSP for latency hiding.
__global__ void __launch_bounds__(160, 3)
vq_mma_kernel(const __grid_constant__ CUtensorMap mxa,
              const __grid_constant__ CUtensorMap mea) {
    extern __shared__ __align__(1024) char smem[];
    uint32_t sbu = smem_u32(smem);
    int tid  = threadIdx.x;
    int wid  = tid >> 5, lane = tid & 31;
    int gid  = lane >> 2, ctg = lane & 3;
    int wm   = (wid >> 1) & 1, wn = wid & 1;   // 2 x 2 compute-warp grid
    int mtile = blockIdx.x, nt = blockIdx.y;

    if (tid == 0) {
        #pragma unroll
        for (int s = 0; s < NBUF; s++) {
            MBARRIER_INIT(BAR_FULL(s), 1);
            MBARRIER_INIT(BAR_EMPTY(s), 4);
        }
    }
    __syncthreads();

    if (wid == 4) {
        // ---------------- producer
        if (lane == 0) {
            int buf = 0, eph = 1;
            for (int s = 0; s < KCH; s++) {
                MBARRIER_WAIT_PARITY_RELAXED(BAR_EMPTY(buf), eph);
                MBARRIER_EXPECT_TX(BAR_FULL(buf), BUF_BYTES);
                uint32_t ab = sbu + buf * BUF_BYTES;
                TMA_LOAD_3D(ab,           &mxa, 0, s, mtile * 128, BAR_FULL(buf));
                TMA_LOAD_3D(ab + A_BYTES, &mea, 0, s, nt * 64,     BAR_FULL(buf));
                if (++buf == NBUF) { buf = 0; eph ^= 1; }
            }
        }
    } else {
        // ---------------- consumers (4 warps, 64x32 each)
        float acc[4][4][4];
        #pragma unroll
        for (int a = 0; a < 4; a++)
            #pragma unroll
            for (int b = 0; b < 4; b++)
                #pragma unroll
                for (int c = 0; c < 4; c++) acc[a][b][c] = 0.0f;

        // ldmatrix per-lane base addresses (offset within buffer).
        // swizzled offset(row, c) = row*128 + ((c ^ (row&7)) << 4); q-step = ^0x20, lo = ^0x40
        int sel = lane >> 3, rin = lane & 7;
        uint32_t a_base[4], b_base[2];
        {
            int arow = (sel & 1) * 8 + rin;
            int ac   = sel >> 1;
            #pragma unroll
            for (int mf = 0; mf < 4; mf++) {
                int row = wm * 64 + mf * 16 + arow;
                a_base[mf] = (uint32_t)(row * 128 + ((ac ^ (row & 7)) << 4));
            }
            int bnr = (sel >> 1) * 8 + rin;
            int bc  = sel & 1;
            #pragma unroll
            for (int np = 0; np < 2; np++) {
                int n = wn * 32 + np * 16 + bnr;
                b_base[np] = (uint32_t)(A_BYTES + n * 128 + ((bc ^ (n & 7)) << 4));
            }
        }

        int buf = 0, fph = 0;
        #pragma unroll 1
        for (int s = 0; s < KCH; s++) {
            MBARRIER_WAIT_PARITY(BAR_FULL(buf), fph);
            uint32_t bb = sbu + buf * BUF_BYTES;

            #pragma unroll
            for (int q = 0; q < 2; q++) {
                uint32_t xq = (uint32_t)(q << 5);
                uint32_t ah[4][4], al[4][4];
                #pragma unroll
                for (int mf = 0; mf < 4; mf++) {
                    LDSM4(ah[mf], bb + (a_base[mf] ^ xq));
                    LDSM4(al[mf], bb + (a_base[mf] ^ xq ^ 0x40u));
                }
                #pragma unroll
                for (int np = 0; np < 2; np++) {
                    uint32_t bh[4], bl[4];
                    LDSM4(bh, bb + (b_base[np] ^ xq));
                    LDSM4(bl, bb + (b_base[np] ^ xq ^ 0x40u));
                    #pragma unroll
                    for (int mf = 0; mf < 4; mf++) {
                        mma16(acc[mf][np * 2],     ah[mf], bh[0], bh[1]);
                        mma16(acc[mf][np * 2 + 1], ah[mf], bh[2], bh[3]);
                    }
                    #pragma unroll
                    for (int mf = 0; mf < 4; mf++) {
                        mma16(acc[mf][np * 2],     ah[mf], bl[0], bl[1]);
                        mma16(acc[mf][np * 2 + 1], ah[mf], bl[2], bl[3]);
                    }
                    #pragma unroll
                    for (int mf = 0; mf < 4; mf++) {
                        mma16(acc[mf][np * 2],     al[mf], bh[0], bh[1]);
                        mma16(acc[mf][np * 2 + 1], al[mf], bh[2], bh[3]);
                    }
                }
            }
            if (lane == 0) MBARRIER_ARRIVE(BAR_EMPTY(buf));
            if (++buf == NBUF) { buf = 0; fph ^= 1; }
        }

        // ---------------- fold scores into packed argmin candidates
        unsigned long long bp8[8];
        #pragma unroll
        for (int r = 0; r < 8; r++) bp8[r] = ~0ULL;

        #pragma unroll
        for (int mf = 0; mf < 4; mf++) {
            #pragma unroll
            for (int nf = 0; nf < 4; nf++) {
                int k0 = nt * 64 + wn * 32 + nf * 8 + ctg * 2;
                float e20 = __ldg(&g_e2[k0]);
                float e21 = __ldg(&g_e2[k0 + 1]);
                float s00 = fmaf(-2.0f, acc[mf][nf][0], e20);
                float s01 = fmaf(-2.0f, acc[mf][nf][1], e21);
                float s10 = fmaf(-2.0f, acc[mf][nf][2], e20);
                float s11 = fmaf(-2.0f, acc[mf][nf][3], e21);
                bp8[mf * 2]     = umin64(bp8[mf * 2],     umin64(packsk(s00, k0), packsk(s01, k0 + 1)));
                bp8[mf * 2 + 1] = umin64(bp8[mf * 2 + 1], umin64(packsk(s10, k0), packsk(s11, k0 + 1)));
            }
        }
        #pragma unroll
        for (int r = 0; r < 8; r++) {
            #pragma unroll
            for (int off = 1; off <= 2; off <<= 1) {
                unsigned long long o = __shfl_xor_sync(0xFFFFFFFFu, bp8[r], off);
                bp8[r] = umin64(bp8[r], o);
            }
        }
        __syncthreads();                         // pipeline drained; reuse smem
        unsigned long long* sp = (unsigned long long*)smem;   // [128][2]
        if (ctg == 0) {
            #pragma unroll
            for (int mf = 0; mf < 4; mf++) {
                int r0 = wm * 64 + mf * 16 + gid;
                sp[r0 * 2 + wn]       = bp8[mf * 2];
                sp[(r0 + 8) * 2 + wn] = bp8[mf * 2 + 1];
            }
        }
    }
    __syncthreads();
    if (tid < 128) {
        unsigned long long* sp = (unsigned long long*)smem;
        unsigned long long v = umin64(sp[tid * 2], sp[tid * 2 + 1]);
        atomicMin(&g_best[mtile * 128 + tid], v);
    }
}

// ---------------------------------------------------------------- gather + codes
// grid (BT/32, DD/128): block = 32 tokens x 128 d-range (4 chunks of 32).
__global__ void __launch_bounds__(256)
gather_kernel(float* __restrict__ qout, float* __restrict__ codes_f) {
    __shared__ float tile[32][33];
    __shared__ int   cs[32];

    int r0  = blockIdx.x * 32;
    int d0b = blockIdx.y * 128;
    int b   = r0 / TT;
    int t0  = r0 % TT;
    int tid = threadIdx.x;
    int lane = tid & 31, w = tid >> 5;

    if (tid < 32) {
        int c = (int)(g_best[r0 + tid] & 0xFFFFFFFFULL);
        cs[tid] = c;
        if (codes_f && blockIdx.y == 0) codes_f[r0 + tid] = (float)c;
    }
    __syncthreads();

    float* obase = qout + (size_t)b * DD * TT + t0;

    for (int d0 = d0b; d0 < d0b + 128; d0 += 32) {
        #pragma unroll
        for (int mm = 0; mm < 4; mm++) {
            int m = w + mm * 8;
            tile[m][lane] = g_emb[(size_t)cs[m] * DD + d0 + lane];
        }
        __syncthreads();
        #pragma unroll
        for (int q = 0; q < 4; q++) {
            int ddr = w * 4 + q;
            obase[(size_t)(d0 + ddr) * TT + lane] = tile[lane][ddr];
        }
        __syncthreads();
    }
}

// ---------------------------------------------------------------- host launch
typedef CUresult (*PFN_encodeTiled)(CUtensorMap*, CUtensorMapDataType, unsigned int,
                                    void*, const unsigned long long*, const unsigned long long*,
                                    const unsigned int*, const unsigned int*,
                                    CUtensorMapInterleave, CUtensorMapSwizzle,
                                    CUtensorMapL2promotion, CUtensorMapFloatOOBfill);

static void encode_map3(PFN_encodeTiled fn, CUtensorMap* m, void* ptr,
                        unsigned long long rows, unsigned int box_z) {
    unsigned long long dims[3]    = {64, KCH, rows};
    unsigned long long strides[2] = {128, (unsigned long long)KCH * 128};
    unsigned int box[3]           = {64, 1, box_z};
    unsigned int es[3]            = {1, 1, 1};
    fn(m, CU_TENSOR_MAP_DATA_TYPE_FLOAT16, 3, ptr, dims, strides, box, es,
       CU_TENSOR_MAP_INTERLEAVE_NONE, CU_TENSOR_MAP_SWIZZLE_128B,
       CU_TENSOR_MAP_L2_PROMOTION_L2_128B, CU_TENSOR_MAP_FLOAT_OOB_FILL_NONE);
}

extern "C" void kernel_launch(void* const* d_in, const int* in_sizes, int n_in,
                              void* d_out, int out_size) {
    const float* x    = nullptr;
    const float* esum = nullptr;
    const float* us   = nullptr;
    for (int i = 0; i < n_in; i++) {
        if      (in_sizes[i] == BDT)     x    = (const float*)d_in[i];
        else if (in_sizes[i] == KK * DD) esum = (const float*)d_in[i];
        else if (in_sizes[i] == KK)      us   = (const float*)d_in[i];
    }

    float* out = (float*)d_out;
    bool concat = (out_size >= BT + BDT);
    float* codes_f = concat ? out : nullptr;
    float* quant   = concat ? out + BT : out;

    PFN_encodeTiled fn = nullptr;
    cudaDriverEntryPointQueryResult st;
    cudaGetDriverEntryPointByVersion("cuTensorMapEncodeTiled", (void**)&fn, 12000,
                                     cudaEnableDefault, &st);

    void *pxa, *pea;
    cudaGetSymbolAddress(&pxa, g_xa);
    cudaGetSymbolAddress(&pea, g_ea);

    CUtensorMap mxa, mea;
    encode_map3(fn, &mxa, pxa, BT, 128);
    encode_map3(fn, &mea, pea, KK, 64);

    prep_all_kernel<<<KK / 2 + BB * KCH * (TT / 64), 256>>>(esum, us, x);

    cudaFuncSetAttribute(vq_mma_kernel, cudaFuncAttributeMaxDynamicSharedMemorySize, SMEM_TOTAL);
    vq_mma_kernel<<<dim3(BT / 128, KK / 64), 160, SMEM_TOTAL>>>(mxa, mea);

    gather_kernel<<<dim3(BT / 32, DD / 128), 256>>>(quant, codes_f);
}

// round 17
// speedup vs baseline: 1.5404x; 1.5404x over previous
#include <cuda_runtime.h>
#include <cuda.h>
#include <cuda_fp16.h>
#include <cstdint>

// ---------------------------------------------------------------- constants
#define BB   16
#define DD   512
#define TT   1024
#define KK   8192
#define BT   (BB * TT)
#define BDT  (BB * DD * TT)

#define EPSV 1e-5f
#define SCALE 16.0f             // argmin-invariant scaling (avoids fp16 subnormal lo)

#define KCH  16                 // 512 / 32 k-chunks
#define NBUF 3
#define A_BYTES 16384           // 128 rows x 128B
#define B_BYTES 8192            // 64 rows x 128B
#define BUF_BYTES (A_BYTES + B_BYTES)          // 24576
#define SMEM_BARS (NBUF * BUF_BYTES)           // 73728
#define SMEM_TOTAL (SMEM_BARS + 64)

#define BAR_FULL(s)  (sbu + SMEM_BARS + (s) * 8)
#define BAR_EMPTY(s) (sbu + SMEM_BARS + 24 + (s) * 8)

// ---------------------------------------------------------------- scratch
__device__ float  g_emb[(size_t)KK * DD];       // fp32 codebook (gather)
__device__ __half g_ea[(size_t)KK * KCH * 64];  // emb: [code][kc][hi x32 | lo x32]
__device__ __half g_xa[(size_t)BT * KCH * 64];  // x:   [token][kc][hi x32 | lo x32]
__device__ float  g_e2[KK];                     // 256 * ||e||^2
__device__ unsigned long long g_best[BT];       // packed (ordered-score << 32 | k)

// ---------------------------------------------------------------- helpers
__device__ __forceinline__ uint32_t smem_u32(const void* p) {
    uint32_t a;
    asm("{ .reg .u64 t; cvta.to.shared.u64 t, %1; cvt.u32.u64 %0, t; }" : "=r"(a) : "l"(p));
    return a;
}

#define MBARRIER_INIT(a, c) \
    asm volatile("mbarrier.init.shared.b64 [%0], %1;" :: "r"((uint32_t)(a)), "r"((uint32_t)(c)) : "memory")
#define MBARRIER_EXPECT_TX(a, b) \
    asm volatile("mbarrier.arrive.expect_tx.shared.b64 _, [%0], %1;" :: "r"((uint32_t)(a)), "r"((uint32_t)(b)) : "memory")
#define MBARRIER_ARRIVE(a) \
    asm volatile("mbarrier.arrive.shared.b64 _, [%0];" :: "r"((uint32_t)(a)) : "memory")

#define MBARRIER_WAIT_PARITY(mbar, ph) do { \
    uint32_t _m = (uint32_t)(mbar), _p = (uint32_t)(ph); \
    asm volatile("{\n\t.reg .pred P1;\n\t" \
        "WL_%=:\n\t" \
        "mbarrier.try_wait.parity.acquire.cta.shared::cta.b64 P1, [%0], %1, 0x989680;\n\t" \
        "@P1 bra.uni WD_%=;\n\tbra.uni WL_%=;\n\tWD_%=:\n\t}" \
        :: "r"(_m), "r"(_p) : "memory"); \
} while (0)

#define MBARRIER_WAIT_PARITY_RELAXED(mbar, ph) do { \
    uint32_t _m = (uint32_t)(mbar), _p = (uint32_t)(ph); \
    asm volatile("{\n\t.reg .pred P1;\n\t" \
        "WL_%=:\n\t" \
        "mbarrier.try_wait.parity.relaxed.cta.shared::cta.b64 P1, [%0], %1, 0x989680;\n\t" \
        "@P1 bra.uni WD_%=;\n\tbra.uni WL_%=;\n\tWD_%=:\n\t}" \
        :: "r"(_m), "r"(_p) : "memory"); \
} while (0)

#define TMA_LOAD_3D(dst, map, cx, cy, cz, mb) \
    asm volatile("cp.async.bulk.tensor.3d.shared::cta.global.tile.mbarrier::complete_tx::bytes " \
        "[%0], [%1, {%2, %3, %4}], [%5];" \
        :: "r"((uint32_t)(dst)), "l"(map), "r"((int)(cx)), "r"((int)(cy)), "r"((int)(cz)), \
           "r"((uint32_t)(mb)) : "memory")

#define LDSM4(r, addr) \
    asm volatile("ldmatrix.sync.aligned.m8n8.x4.shared.b16 {%0,%1,%2,%3}, [%4];" \
        : "=r"((r)[0]), "=r"((r)[1]), "=r"((r)[2]), "=r"((r)[3]) : "r"((uint32_t)(addr)))

__device__ __forceinline__ void mma16(float* d, const uint32_t* a,
                                      uint32_t b0, uint32_t b1) {
    asm volatile(
        "mma.sync.aligned.m16n8k16.row.col.f32.f16.f16.f32 "
        "{%0,%1,%2,%3}, {%4,%5,%6,%7}, {%8,%9}, {%0,%1,%2,%3};"
        : "+f"(d[0]), "+f"(d[1]), "+f"(d[2]), "+f"(d[3])
        : "r"(a[0]), "r"(a[1]), "r"(a[2]), "r"(a[3]), "r"(b0), "r"(b1));
}

__device__ __forceinline__ unsigned long long packsk(float s, int k) {
    uint32_t u = __float_as_uint(s);
    u ^= (uint32_t)((int32_t)u >> 31) | 0x80000000u;
    return ((unsigned long long)u << 32) | (uint32_t)k;
}
__device__ __forceinline__ unsigned long long umin64(unsigned long long a,
                                                     unsigned long long b) {
    return a < b ? a : b;
}

// ---------------------------------------------------------------- merged prep
// blocks [0, KK/2): emb prep (2 codes per 256-thread block), 8B packed ea stores
// blocks [KK/2, KK/2 + BB*KCH*(TT/64)): x transpose + split, 64 tokens x 32 d
__global__ void __launch_bounds__(256)
prep_all_kernel(const float* __restrict__ esum,
                const float* __restrict__ usage,
                const float* __restrict__ x) {
    int bid = blockIdx.x;
    if (bid < KK / 2) {
        int tid128 = threadIdx.x & 127;
        int k = bid * 2 + (threadIdx.x >> 7);
        float inv = 1.0f / fmaxf(usage[k], EPSV);

        float4 v = ((const float4*)(esum + (size_t)k * DD))[tid128];
        v.x *= inv; v.y *= inv; v.z *= inv; v.w *= inv;
        ((float4*)(g_emb + (size_t)k * DD))[tid128] = v;

        int d  = tid128 * 4;
        int kc = d >> 5, j = d & 31;
        __half* row = g_ea + ((size_t)k * KCH + kc) * 64;
        float vv[4] = {v.x, v.y, v.z, v.w};
        __half2 hh[2], ll[2];
        #pragma unroll
        for (int c = 0; c < 2; c++) {
            float f0 = vv[2 * c] * SCALE;
            float f1 = vv[2 * c + 1] * SCALE;
            __half h0 = __float2half_rn(f0);
            __half h1 = __float2half_rn(f1);
            __half l0 = __float2half_rn(f0 - __half2float(h0));
            __half l1 = __float2half_rn(f1 - __half2float(h1));
            hh[c] = __halves2half2(h0, h1);
            ll[c] = __halves2half2(l0, l1);
        }
        *(uint2*)(row + j)      = *(uint2*)hh;
        *(uint2*)(row + 32 + j) = *(uint2*)ll;

        float s = v.x * v.x + v.y * v.y + v.z * v.z + v.w * v.w;
        #pragma unroll
        for (int off = 16; off > 0; off >>= 1)
            s += __shfl_down_sync(0xFFFFFFFFu, s, off);

        __shared__ float ws[8];
        int lane = threadIdx.x & 31, w = threadIdx.x >> 5;
        if (lane == 0) ws[w] = s;
        __syncthreads();
        if (tid128 == 0) {
            int w0 = (threadIdx.x >> 7) * 4;
            g_e2[k] = (SCALE * SCALE) * (ws[w0] + ws[w0 + 1] + ws[w0 + 2] + ws[w0 + 3]);
        }
    } else {
        __shared__ float tile[32][65];
        int xid = bid - KK / 2;
        int b    = xid >> 8;
        int kc   = (xid >> 4) & 15;
        int t0   = (xid & 15) * 64;
        int tid  = threadIdx.x;
        int lane = tid & 31, w = tid >> 5;

        const float* xb = x + ((size_t)b * DD + kc * 32) * TT + t0;
        #pragma unroll
        for (int i = 0; i < 4; i++) {
            int row = w + i * 8;
            float2 v = *(const float2*)(xb + (size_t)row * TT + lane * 2);
            tile[row][lane * 2]     = v.x;
            tile[row][lane * 2 + 1] = v.y;
        }
        if (kc == 0 && tid < 64) g_best[b * TT + t0 + tid] = ~0ULL;
        __syncthreads();

        int tok = tid >> 2;
        int dg  = (tid & 3) * 8;
        __half2 h2[4], l2[4];
        #pragma unroll
        for (int j = 0; j < 4; j++) {
            float f0 = tile[dg + 2 * j][tok] * SCALE;
            float f1 = tile[dg + 2 * j + 1][tok] * SCALE;
            __half h0 = __float2half_rn(f0);
            __half h1 = __float2half_rn(f1);
            __half l0 = __float2half_rn(f0 - __half2float(h0));
            __half l1 = __float2half_rn(f1 - __half2float(h1));
            h2[j] = __halves2half2(h0, h1);
            l2[j] = __halves2half2(l0, l1);
        }
        size_t row = ((size_t)(b * TT + t0 + tok) * KCH + kc) * 64;
        *(uint4*)(g_xa + row + dg)      = *(uint4*)h2;
        *(uint4*)(g_xa + row + 32 + dg) = *(uint4*)l2;
    }
}

// ---------------------------------------------------------------- GEMM + argmin (R10/R12 proven config)
// CTA: 128(M) x 64(N), 4 consumer warps (warp tile 64x32) + 1 producer.
// 3 CTAs / SM (72KB smem) -> 3 consumer warps/SMSP for latency hiding.
__global__ void __launch_bounds__(160, 3)
vq_mma_kernel(const __grid_constant__ CUtensorMap mxa,
              const __grid_constant__ CUtensorMap mea) {
    extern __shared__ __align__(1024) char smem[];
    uint32_t sbu = smem_u32(smem);
    int tid  = threadIdx.x;
    int wid  = tid >> 5, lane = tid & 31;
    int gid  = lane >> 2, ctg = lane & 3;
    int wm   = (wid >> 1) & 1, wn = wid & 1;   // 2 x 2 compute-warp grid
    int mtile = blockIdx.x, nt = blockIdx.y;

    if (tid == 0) {
        #pragma unroll
        for (int s = 0; s < NBUF; s++) {
            MBARRIER_INIT(BAR_FULL(s), 1);
            MBARRIER_INIT(BAR_EMPTY(s), 4);
        }
    }
    __syncthreads();

    if (wid == 4) {
        // ---------------- producer
        if (lane == 0) {
            int buf = 0, eph = 1;
            for (int s = 0; s < KCH; s++) {
                MBARRIER_WAIT_PARITY_RELAXED(BAR_EMPTY(buf), eph);
                MBARRIER_EXPECT_TX(BAR_FULL(buf), BUF_BYTES);
                uint32_t ab = sbu + buf * BUF_BYTES;
                TMA_LOAD_3D(ab,           &mxa, 0, s, mtile * 128, BAR_FULL(buf));
                TMA_LOAD_3D(ab + A_BYTES, &mea, 0, s, nt * 64,     BAR_FULL(buf));
                if (++buf == NBUF) { buf = 0; eph ^= 1; }
            }
        }
    } else {
        // ---------------- consumers (4 warps, 64x32 each)
        float acc[4][4][4];
        #pragma unroll
        for (int a = 0; a < 4; a++)
            #pragma unroll
            for (int b = 0; b < 4; b++)
                #pragma unroll
                for (int c = 0; c < 4; c++) acc[a][b][c] = 0.0f;

        // ldmatrix per-lane base addresses (offset within buffer).
        // swizzled offset(row, c) = row*128 + ((c ^ (row&7)) << 4); q-step = ^0x20, lo = ^0x40
        int sel = lane >> 3, rin = lane & 7;
        uint32_t a_base[4], b_base[2];
        {
            int arow = (sel & 1) * 8 + rin;
            int ac   = sel >> 1;
            #pragma unroll
            for (int mf = 0; mf < 4; mf++) {
                int row = wm * 64 + mf * 16 + arow;
                a_base[mf] = (uint32_t)(row * 128 + ((ac ^ (row & 7)) << 4));
            }
            int bnr = (sel >> 1) * 8 + rin;
            int bc  = sel & 1;
            #pragma unroll
            for (int np = 0; np < 2; np++) {
                int n = wn * 32 + np * 16 + bnr;
                b_base[np] = (uint32_t)(A_BYTES + n * 128 + ((bc ^ (n & 7)) << 4));
            }
        }

        int buf = 0, fph = 0;
        #pragma unroll 1
        for (int s = 0; s < KCH; s++) {
            MBARRIER_WAIT_PARITY(BAR_FULL(buf), fph);
            uint32_t bb = sbu + buf * BUF_BYTES;

            #pragma unroll
            for (int q = 0; q < 2; q++) {
                uint32_t xq = (uint32_t)(q << 5);
                uint32_t ah[4][4], al[4][4];
                #pragma unroll
                for (int mf = 0; mf < 4; mf++) {
                    LDSM4(ah[mf], bb + (a_base[mf] ^ xq));
                    LDSM4(al[mf], bb + (a_base[mf] ^ xq ^ 0x40u));
                }
                #pragma unroll
                for (int np = 0; np < 2; np++) {
                    uint32_t bh[4], bl[4];
                    LDSM4(bh, bb + (b_base[np] ^ xq));
                    LDSM4(bl, bb + (b_base[np] ^ xq ^ 0x40u));
                    #pragma unroll
                    for (int mf = 0; mf < 4; mf++) {
                        mma16(acc[mf][np * 2],     ah[mf], bh[0], bh[1]);
                        mma16(acc[mf][np * 2 + 1], ah[mf], bh[2], bh[3]);
                    }
                    #pragma unroll
                    for (int mf = 0; mf < 4; mf++) {
                        mma16(acc[mf][np * 2],     ah[mf], bl[0], bl[1]);
                        mma16(acc[mf][np * 2 + 1], ah[mf], bl[2], bl[3]);
                    }
                    #pragma unroll
                    for (int mf = 0; mf < 4; mf++) {
                        mma16(acc[mf][np * 2],     al[mf], bh[0], bh[1]);
                        mma16(acc[mf][np * 2 + 1], al[mf], bh[2], bh[3]);
                    }
                }
            }
            if (lane == 0) MBARRIER_ARRIVE(BAR_EMPTY(buf));
            if (++buf == NBUF) { buf = 0; fph ^= 1; }
        }

        // ---------------- fold scores into packed argmin candidates
        unsigned long long bp8[8];
        #pragma unroll
        for (int r = 0; r < 8; r++) bp8[r] = ~0ULL;

        #pragma unroll
        for (int mf = 0; mf < 4; mf++) {
            #pragma unroll
            for (int nf = 0; nf < 4; nf++) {
                int k0 = nt * 64 + wn * 32 + nf * 8 + ctg * 2;
                float e20 = __ldg(&g_e2[k0]);
                float e21 = __ldg(&g_e2[k0 + 1]);
                float s00 = fmaf(-2.0f, acc[mf][nf][0], e20);
                float s01 = fmaf(-2.0f, acc[mf][nf][1], e21);
                float s10 = fmaf(-2.0f, acc[mf][nf][2], e20);
                float s11 = fmaf(-2.0f, acc[mf][nf][3], e21);
                bp8[mf * 2]     = umin64(bp8[mf * 2],     umin64(packsk(s00, k0), packsk(s01, k0 + 1)));
                bp8[mf * 2 + 1] = umin64(bp8[mf * 2 + 1], umin64(packsk(s10, k0), packsk(s11, k0 + 1)));
            }
        }
        #pragma unroll
        for (int r = 0; r < 8; r++) {
            #pragma unroll
            for (int off = 1; off <= 2; off <<= 1) {
                unsigned long long o = __shfl_xor_sync(0xFFFFFFFFu, bp8[r], off);
                bp8[r] = umin64(bp8[r], o);
            }
        }
        __syncthreads();                         // pipeline drained; reuse smem
        unsigned long long* sp = (unsigned long long*)smem;   // [128][2]
        if (ctg == 0) {
            #pragma unroll
            for (int mf = 0; mf < 4; mf++) {
                int r0 = wm * 64 + mf * 16 + gid;
                sp[r0 * 2 + wn]       = bp8[mf * 2];
                sp[(r0 + 8) * 2 + wn] = bp8[mf * 2 + 1];
            }
        }
    }
    __syncthreads();
    if (tid < 128) {
        unsigned long long* sp = (unsigned long long*)smem;
        unsigned long long v = umin64(sp[tid * 2], sp[tid * 2 + 1]);
        atomicMin(&g_best[mtile * 128 + tid], v);
    }
}

// ---------------------------------------------------------------- gather + codes
// grid (BT/32, DD/128): block = 32 tokens x 128 d-range (4 chunks of 32).
__global__ void __launch_bounds__(256)
gather_kernel(float* __restrict__ qout, float* __restrict__ codes_f) {
    __shared__ float tile[32][33];
    __shared__ int   cs[32];

    int r0  = blockIdx.x * 32;
    int d0b = blockIdx.y * 128;
    int b   = r0 / TT;
    int t0  = r0 % TT;
    int tid = threadIdx.x;
    int lane = tid & 31, w = tid >> 5;

    if (tid < 32) {
        int c = (int)(g_best[r0 + tid] & 0xFFFFFFFFULL);
        cs[tid] = c;
        if (codes_f && blockIdx.y == 0) codes_f[r0 + tid] = (float)c;
    }
    __syncthreads();

    float* obase = qout + (size_t)b * DD * TT + t0;

    for (int d0 = d0b; d0 < d0b + 128; d0 += 32) {
        #pragma unroll
        for (int mm = 0; mm < 4; mm++) {
            int m = w + mm * 8;
            tile[m][lane] = g_emb[(size_t)cs[m] * DD + d0 + lane];
        }
        __syncthreads();
        #pragma unroll
        for (int q = 0; q < 4; q++) {
            int ddr = w * 4 + q;
            obase[(size_t)(d0 + ddr) * TT + lane] = tile[lane][ddr];
        }
        __syncthreads();
    }
}

// ---------------------------------------------------------------- host launch
typedef CUresult (*PFN_encodeTiled)(CUtensorMap*, CUtensorMapDataType, unsigned int,
                                    void*, const unsigned long long*, const unsigned long long*,
                                    const unsigned int*, const unsigned int*,
                                    CUtensorMapInterleave, CUtensorMapSwizzle,
                                    CUtensorMapL2promotion, CUtensorMapFloatOOBfill);

static void encode_map3(PFN_encodeTiled fn, CUtensorMap* m, void* ptr,
                        unsigned long long rows, unsigned int box_z) {
    unsigned long long dims[3]    = {64, KCH, rows};
    unsigned long long strides[2] = {128, (unsigned long long)KCH * 128};
    unsigned int box[3]           = {64, 1, box_z};
    unsigned int es[3]            = {1, 1, 1};
    fn(m, CU_TENSOR_MAP_DATA_TYPE_FLOAT16, 3, ptr, dims, strides, box, es,
       CU_TENSOR_MAP_INTERLEAVE_NONE, CU_TENSOR_MAP_SWIZZLE_128B,
       CU_TENSOR_MAP_L2_PROMOTION_L2_128B, CU_TENSOR_MAP_FLOAT_OOB_FILL_NONE);
}

extern "C" void kernel_launch(void* const* d_in, const int* in_sizes, int n_in,
                              void* d_out, int out_size) {
    const float* x    = nullptr;
    const float* esum = nullptr;
    const float* us   = nullptr;
    for (int i = 0; i < n_in; i++) {
        if      (in_sizes[i] == BDT)     x    = (const float*)d_in[i];
        else if (in_sizes[i] == KK * DD) esum = (const float*)d_in[i];
        else if (in_sizes[i] == KK)      us   = (const float*)d_in[i];
    }

    float* out = (float*)d_out;
    bool concat = (out_size >= BT + BDT);
    float* codes_f = concat ? out : nullptr;
    float* quant   = concat ? out + BT : out;

    PFN_encodeTiled fn = nullptr;
    cudaDriverEntryPointQueryResult st;
    cudaGetDriverEntryPointByVersion("cuTensorMapEncodeTiled", (void**)&fn, 12000,
                                     cudaEnableDefault, &st);

    void *pxa, *pea;
    cudaGetSymbolAddress(&pxa, g_xa);
    cudaGetSymbolAddress(&pea, g_ea);

    CUtensorMap mxa, mea;
    encode_map3(fn, &mxa, pxa, BT, 128);
    encode_map3(fn, &mea, pea, KK, 64);

    prep_all_kernel<<<KK / 2 + BB * KCH * (TT / 64), 256>>>(esum, us, x);

    cudaFuncSetAttribute(vq_mma_kernel, cudaFuncAttributeMaxDynamicSharedMemorySize, SMEM_TOTAL);
    vq_mma_kernel<<<dim3(BT / 128, KK / 64), 160, SMEM_TOTAL>>>(mxa, mea);

    gather_kernel<<<dim3(BT / 32, DD / 128), 256>>>(quant, codes_f);
}